// round 10
// baseline (speedup 1.0000x reference)
#include <cuda_runtime.h>
#include <cstdint>

typedef unsigned long long ull;

#define STATE_DIM 64
#define HID       256
#define AH        256
#define ADIM      8
#define BATCH     1024
#define TSTEPS    512

#define CLUSTER_C 8
#define HS        32          // hidden units per CTA
#define MT        64          // batch rows per cluster group
#define NGROUP    (BATCH/MT)  // 16
#define GRID_SZ   (NGROUP*CLUSTER_C) // 128
#define NTHREADS  256

#define HPAD 258              // h row stride (floats): conflict-free LDS.64
#define XPAD 66               // x row stride (floats)

#define SMEM_FLOATS (3*HS*HPAD + 3*HS*XPAD + MT*HPAD + 2*MT*XPAD)
#define SMEM_BYTES  (SMEM_FLOATS*4)

__device__ float g_hT[BATCH*HID];   // h_T scratch (1 MB)

// ---------------- helpers ----------------
__device__ __forceinline__ uint32_t smem_u32(const void* p){
    uint32_t a;
    asm("{ .reg .u64 t; cvta.to.shared.u64 t, %1; cvt.u32.u64 %0, t; }" : "=r"(a) : "l"(p));
    return a;
}
__device__ __forceinline__ void fma2(ull &acc, ull a, ull b){
    asm("fma.rn.f32x2 %0, %1, %2, %0;" : "+l"(acc) : "l"(a), "l"(b));
}
__device__ __forceinline__ float red2(ull v){
    float x, y;
    asm("mov.b64 {%0, %1}, %2;" : "=f"(x), "=f"(y) : "l"(v));
    return x + y;
}
__device__ __forceinline__ ull pack2(float x, float y){
    ull v; asm("mov.b64 %0, {%1, %2};" : "=l"(v) : "f"(x), "f"(y)); return v;
}
__device__ __forceinline__ float sigf(float x){
    return __fdividef(1.f, 1.f + __expf(-x));
}
__device__ __forceinline__ float tanhf_fast(float x){
    // robust at +/-inf of exp: 1 - 2/(e^{2x}+1)
    return 1.f - __fdividef(2.f, __expf(2.f*x) + 1.f);
}
__device__ __forceinline__ void cluster_sync_(){
    asm volatile("barrier.cluster.arrive.aligned;" ::: "memory");
    asm volatile("barrier.cluster.wait.aligned;" ::: "memory");
}

// ---------------- GRU recurrence ----------------
// Cluster of 8 CTAs per batch group of 64 rows.
// CTA rank owns hidden slice [rank*32, rank*32+32): gate rows r/z/n for that slice
// live in smem for the whole kernel. Full h (64x256) replicated in each CTA's smem,
// refreshed each step via DSMEM broadcast.
__global__ void __launch_bounds__(NTHREADS, 1) __cluster_dims__(CLUSTER_C, 1, 1)
gru_kernel(const float* __restrict__ x_seq, const float* __restrict__ w_ih,
           const float* __restrict__ w_hh, const float* __restrict__ b_ih,
           const float* __restrict__ b_hh)
{
    extern __shared__ float smem[];
    float* sWh = smem;                       // [3*HS][HPAD]
    float* sWx = sWh + 3*HS*HPAD;            // [3*HS][XPAD]
    float* sh  = sWx + 3*HS*XPAD;            // [MT][HPAD]   full h, replicated
    float* sx  = sh  + MT*HPAD;              // [2][MT][XPAD] double-buffered x_t

    const int tid  = threadIdx.x;
    const int tm   = tid & 15;               // thread handles m = tm, tm+16, tm+32, tm+48
    const int tj   = tid >> 4;               // thread handles j = 2*tj, 2*tj+1 (local)
    const int rank = blockIdx.x & (CLUSTER_C-1);
    const int grp  = blockIdx.x >> 3;
    const int jg0  = rank*HS + 2*tj;         // global hidden index of jj=0

    // --- load weight slices into smem ---
    for (int idx = tid; idx < 3*HS*HID; idx += NTHREADS) {
        int k = idx & (HID-1); int row = idx >> 8;   // row = g*HS + jloc
        sWh[row*HPAD + k] = w_hh[((row>>5)*HID + rank*HS + (row&31))*HID + k];
    }
    for (int idx = tid; idx < 3*HS*STATE_DIM; idx += NTHREADS) {
        int k = idx & (STATE_DIM-1); int row = idx >> 6;
        sWx[row*XPAD + k] = w_ih[((row>>5)*HID + rank*HS + (row&31))*STATE_DIM + k];
    }
    for (int idx = tid; idx < MT*HPAD; idx += NTHREADS) sh[idx] = 0.f;

    // --- biases (per-thread registers) ---
    float b_r[2], b_z[2], b_in[2], b_hn[2];
    #pragma unroll
    for (int jj = 0; jj < 2; jj++) {
        int jg = jg0 + jj;
        b_r[jj]  = b_ih[jg]        + b_hh[jg];
        b_z[jj]  = b_ih[HID+jg]    + b_hh[HID+jg];
        b_in[jj] = b_ih[2*HID+jg];
        b_hn[jj] = b_hh[2*HID+jg];
    }

    // --- x(t=0) into buffer 0 ---
    {
        int r = tid >> 2, c = (tid & 3) << 4;
        const float4* src = (const float4*)(x_seq + ((size_t)(grp*MT + r))*TSTEPS*STATE_DIM + c);
        float4 a0 = src[0], a1 = src[1], a2 = src[2], a3 = src[3];
        float* d = sx + r*XPAD + c;
        ((float2*)d)[0] = make_float2(a0.x,a0.y); ((float2*)d)[1] = make_float2(a0.z,a0.w);
        ((float2*)d)[2] = make_float2(a1.x,a1.y); ((float2*)d)[3] = make_float2(a1.z,a1.w);
        ((float2*)d)[4] = make_float2(a2.x,a2.y); ((float2*)d)[5] = make_float2(a2.z,a2.w);
        ((float2*)d)[6] = make_float2(a3.x,a3.y); ((float2*)d)[7] = make_float2(a3.z,a3.w);
    }

    // --- DSMEM broadcast destinations (stable across the loop) ---
    uint32_t sh_addr = smem_u32(sh);
    uint32_t dstb[CLUSTER_C];
    #pragma unroll
    for (int r2 = 0; r2 < CLUSTER_C; r2++)
        asm("mapa.shared::cluster.u32 %0, %1, %2;" : "=r"(dstb[r2]) : "r"(sh_addr), "r"(r2));

    const ull* sh2  = (const ull*)sh;
    const ull* sWh2 = (const ull*)sWh;
    const ull* sWx2 = (const ull*)sWx;

    int whr[2], whz[2], whn[2], wxr[2], wxz[2], wxn[2];
    #pragma unroll
    for (int jj = 0; jj < 2; jj++) {
        int j = 2*tj + jj;
        whr[jj] = (0*HS + j)*(HPAD/2);
        whz[jj] = (1*HS + j)*(HPAD/2);
        whn[jj] = (2*HS + j)*(HPAD/2);
        wxr[jj] = (0*HS + j)*(XPAD/2);
        wxz[jj] = (1*HS + j)*(XPAD/2);
        wxn[jj] = (2*HS + j)*(XPAD/2);
    }

    float hnew[4][2];

    for (int t = 0; t < TSTEPS; t++) {
        const int p = t & 1;
        cluster_sync_();                      // h(t) visible; x buf p ready

        // prefetch x(t+1) into registers (latency hidden by compute)
        float4 a0, a1, a2, a3;
        const bool pf = (t+1 < TSTEPS);
        if (pf) {
            int r = tid >> 2, c = (tid & 3) << 4;
            const float4* src = (const float4*)(x_seq +
                (((size_t)(grp*MT + r))*TSTEPS + (t+1))*STATE_DIM + c);
            a0 = src[0]; a1 = src[1]; a2 = src[2]; a3 = src[3];
        }

        ull ar[4][2], az[4][2], an[4][2];
        #pragma unroll
        for (int i = 0; i < 4; i++)
            #pragma unroll
            for (int jj = 0; jj < 2; jj++) { ar[i][jj]=0; az[i][jj]=0; an[i][jj]=0; }

        // ---- h part: K = 256 (packed f32x2) ----
        #pragma unroll 4
        for (int k2 = 0; k2 < HID/2; k2++) {
            ull hv[4];
            #pragma unroll
            for (int i = 0; i < 4; i++) hv[i] = sh2[(tm + 16*i)*(HPAD/2) + k2];
            #pragma unroll
            for (int jj = 0; jj < 2; jj++) {
                ull wr = sWh2[whr[jj] + k2];
                ull wz = sWh2[whz[jj] + k2];
                ull wn = sWh2[whn[jj] + k2];
                #pragma unroll
                for (int i = 0; i < 4; i++) {
                    fma2(ar[i][jj], hv[i], wr);
                    fma2(az[i][jj], hv[i], wz);
                    fma2(an[i][jj], hv[i], wn);
                }
            }
        }

        // n gate's h-part must stay separate (r multiplies it)
        float hn_s[4][2];
        #pragma unroll
        for (int i = 0; i < 4; i++)
            #pragma unroll
            for (int jj = 0; jj < 2; jj++) { hn_s[i][jj] = red2(an[i][jj]); an[i][jj] = 0; }

        // ---- x part: K = 64 ----
        const ull* sxp = (const ull*)(sx + p*(MT*XPAD));
        #pragma unroll 4
        for (int k2 = 0; k2 < STATE_DIM/2; k2++) {
            ull xv[4];
            #pragma unroll
            for (int i = 0; i < 4; i++) xv[i] = sxp[(tm + 16*i)*(XPAD/2) + k2];
            #pragma unroll
            for (int jj = 0; jj < 2; jj++) {
                ull wr = sWx2[wxr[jj] + k2];
                ull wz = sWx2[wxz[jj] + k2];
                ull wn = sWx2[wxn[jj] + k2];
                #pragma unroll
                for (int i = 0; i < 4; i++) {
                    fma2(ar[i][jj], xv[i], wr);
                    fma2(az[i][jj], xv[i], wz);
                    fma2(an[i][jj], xv[i], wn);
                }
            }
        }

        // ---- gates + state update ----
        #pragma unroll
        for (int i = 0; i < 4; i++)
            #pragma unroll
            for (int jj = 0; jj < 2; jj++) {
                float r = sigf(red2(ar[i][jj]) + b_r[jj]);
                float z = sigf(red2(az[i][jj]) + b_z[jj]);
                float n = tanhf_fast(red2(an[i][jj]) + b_in[jj] + r*(hn_s[i][jj] + b_hn[jj]));
                float hold = sh[(tm + 16*i)*HPAD + jg0 + jj];
                hnew[i][jj] = (1.f - z)*n + z*hold;
            }

        // write prefetched x into the other buffer
        if (pf) {
            int r = tid >> 2, c = (tid & 3) << 4;
            float* d = sx + (p^1)*(MT*XPAD) + r*XPAD + c;
            ((float2*)d)[0] = make_float2(a0.x,a0.y); ((float2*)d)[1] = make_float2(a0.z,a0.w);
            ((float2*)d)[2] = make_float2(a1.x,a1.y); ((float2*)d)[3] = make_float2(a1.z,a1.w);
            ((float2*)d)[4] = make_float2(a2.x,a2.y); ((float2*)d)[5] = make_float2(a2.z,a2.w);
            ((float2*)d)[6] = make_float2(a3.x,a3.y); ((float2*)d)[7] = make_float2(a3.z,a3.w);
        }

        cluster_sync_();                      // everyone done reading h(t)

        // broadcast h(t+1) slice to all 8 CTAs of the cluster (DSMEM)
        #pragma unroll
        for (int i = 0; i < 4; i++) {
            ull v = pack2(hnew[i][0], hnew[i][1]);
            uint32_t off = ((uint32_t)(tm + 16*i)*HPAD + (uint32_t)jg0) * 4u;
            #pragma unroll
            for (int r2 = 0; r2 < CLUSTER_C; r2++)
                asm volatile("st.shared::cluster.u64 [%0], %1;"
                             :: "r"(dstb[r2] + off), "l"(v) : "memory");
        }
    }

    cluster_sync_();   // drain in-flight peer DSMEM stores before exit

    // write final h_T (each CTA writes only its own slice, from registers)
    #pragma unroll
    for (int i = 0; i < 4; i++)
        #pragma unroll
        for (int jj = 0; jj < 2; jj++)
            g_hT[(size_t)(grp*MT + tm + 16*i)*HID + jg0 + jj] = hnew[i][jj];
}

// ---------------- heads: relu(h W_b^T + b) -> tanh(dir)*sigmoid(mag) ----------------
__global__ void __launch_bounds__(256)
heads_kernel(const float* __restrict__ w_base, const float* __restrict__ b_base,
             const float* __restrict__ w_dir,  const float* __restrict__ b_dir,
             const float* __restrict__ w_mag,  const float* __restrict__ b_mag,
             float* __restrict__ out)
{
    __shared__ float hrow[HID];
    __shared__ float act[AH];
    const int b = blockIdx.x;
    const int tid = threadIdx.x;

    hrow[tid] = g_hT[(size_t)b*HID + tid];
    __syncthreads();

    float acc = b_base[tid];
    const float* w = w_base + (size_t)tid*HID;
    #pragma unroll 8
    for (int k = 0; k < HID; k++) acc = fmaf(hrow[k], w[k], acc);
    act[tid] = fmaxf(acc, 0.f);
    __syncthreads();

    const int wid = tid >> 5, lane = tid & 31;   // 8 warps -> 8 action dims
    float sd = 0.f, sm = 0.f;
    const float* wd = w_dir + (size_t)wid*AH;
    const float* wm = w_mag + (size_t)wid*AH;
    #pragma unroll
    for (int k = lane; k < AH; k += 32) {
        float a = act[k];
        sd = fmaf(a, wd[k], sd);
        sm = fmaf(a, wm[k], sm);
    }
    #pragma unroll
    for (int off = 16; off > 0; off >>= 1) {
        sd += __shfl_xor_sync(0xffffffffu, sd, off);
        sm += __shfl_xor_sync(0xffffffffu, sm, off);
    }
    if (lane == 0) {
        float dir = tanhf_fast(sd + b_dir[wid]);
        float mag = sigf(sm + b_mag[wid]);
        out[b*ADIM + wid] = dir * mag;
    }
}

// ---------------- launch ----------------
extern "C" void kernel_launch(void* const* d_in, const int* in_sizes, int n_in,
                              void* d_out, int out_size)
{
    (void)in_sizes; (void)n_in; (void)out_size;
    const float* x_seq  = (const float*)d_in[0];
    const float* w_ih   = (const float*)d_in[1];
    const float* w_hh   = (const float*)d_in[2];
    const float* b_ih   = (const float*)d_in[3];
    const float* b_hh   = (const float*)d_in[4];
    const float* w_base = (const float*)d_in[5];
    const float* b_base = (const float*)d_in[6];
    const float* w_dir  = (const float*)d_in[7];
    const float* b_dir  = (const float*)d_in[8];
    const float* w_mag  = (const float*)d_in[9];
    const float* b_mag  = (const float*)d_in[10];
    float* out = (float*)d_out;

    cudaFuncSetAttribute(gru_kernel, cudaFuncAttributeMaxDynamicSharedMemorySize, SMEM_BYTES);
    gru_kernel<<<GRID_SZ, NTHREADS, SMEM_BYTES>>>(x_seq, w_ih, w_hh, b_ih, b_hh);
    heads_kernel<<<BATCH, 256>>>(w_base, b_base, w_dir, b_dir, w_mag, b_mag, out);
}

// round 11
// speedup vs baseline: 1.1187x; 1.1187x over previous
#include <cuda_runtime.h>
#include <cstdint>

typedef unsigned long long ull;

#define STATE_DIM 64
#define HID       256
#define AH        256
#define ADIM      8
#define BATCH     1024
#define TSTEPS    512

#define CLUSTER_C 8
#define HS        32          // hidden units per CTA
#define MT        64          // batch rows per cluster group
#define NGROUP    (BATCH/MT)  // 16
#define GRID_SZ   (NGROUP*CLUSTER_C) // 128
#define NTHREADS  256

#define HPAD 260              // h/w row stride (floats): 16B aligned, 2-phase LDS.128
#define XPAD 68               // x row stride (floats): 16B aligned, 2-phase LDS.128

#define SMEM_FLOATS (3*HS*HPAD + 3*HS*XPAD + MT*HPAD + 2*MT*XPAD)
#define SMEM_BYTES  (SMEM_FLOATS*4)   // 227328 B

__device__ float g_hT[BATCH*HID];   // h_T scratch (1 MB)

// ---------------- helpers ----------------
__device__ __forceinline__ uint32_t smem_u32(const void* p){
    uint32_t a;
    asm("{ .reg .u64 t; cvta.to.shared.u64 t, %1; cvt.u32.u64 %0, t; }" : "=r"(a) : "l"(p));
    return a;
}
__device__ __forceinline__ void fma2(ull &acc, ull a, ull b){
    asm("fma.rn.f32x2 %0, %1, %2, %0;" : "+l"(acc) : "l"(a), "l"(b));
}
__device__ __forceinline__ float red2(ull v){
    float x, y;
    asm("mov.b64 {%0, %1}, %2;" : "=f"(x), "=f"(y) : "l"(v));
    return x + y;
}
__device__ __forceinline__ ull pack2(float x, float y){
    ull v; asm("mov.b64 %0, {%1, %2};" : "=l"(v) : "f"(x), "f"(y)); return v;
}
__device__ __forceinline__ float sigf(float x){
    return __fdividef(1.f, 1.f + __expf(-x));
}
__device__ __forceinline__ float tanhf_fast(float x){
    return 1.f - __fdividef(2.f, __expf(2.f*x) + 1.f);
}
__device__ __forceinline__ void cluster_sync_(){
    asm volatile("barrier.cluster.arrive.aligned;" ::: "memory");
    asm volatile("barrier.cluster.wait.aligned;" ::: "memory");
}

// ---------------- GRU recurrence ----------------
// Cluster of 8 CTAs per batch group of 64 rows. CTA rank owns hidden slice
// [rank*32, rank*32+32). W slices smem-resident; full h replicated per CTA,
// refreshed each step via DSMEM broadcast.
// Per-step order: x-GEMM(t) | prefetch x(t+1) | syncA | h-GEMM(t) | gates |
// stage x(t+1) | syncB | broadcast h(t+1)  -- broadcast drain overlaps the
// next iteration's x-GEMM.
__global__ void __launch_bounds__(NTHREADS, 1) __cluster_dims__(CLUSTER_C, 1, 1)
gru_kernel(const float* __restrict__ x_seq, const float* __restrict__ w_ih,
           const float* __restrict__ w_hh, const float* __restrict__ b_ih,
           const float* __restrict__ b_hh)
{
    extern __shared__ float smem[];
    float* sWh = smem;                       // [3*HS][HPAD]
    float* sWx = sWh + 3*HS*HPAD;            // [3*HS][XPAD]
    float* sh  = sWx + 3*HS*XPAD;            // [MT][HPAD]
    float* sx  = sh  + MT*HPAD;              // [2][MT][XPAD]

    const int tid  = threadIdx.x;
    const int tm   = tid & 15;
    const int tj   = tid >> 4;
    const int rank = blockIdx.x & (CLUSTER_C-1);
    const int grp  = blockIdx.x >> 3;
    const int jg0  = rank*HS + 2*tj;

    // --- load weight slices into smem ---
    for (int idx = tid; idx < 3*HS*HID; idx += NTHREADS) {
        int k = idx & (HID-1); int row = idx >> 8;
        sWh[row*HPAD + k] = w_hh[((row>>5)*HID + rank*HS + (row&31))*HID + k];
    }
    for (int idx = tid; idx < 3*HS*STATE_DIM; idx += NTHREADS) {
        int k = idx & (STATE_DIM-1); int row = idx >> 6;
        sWx[row*XPAD + k] = w_ih[((row>>5)*HID + rank*HS + (row&31))*STATE_DIM + k];
    }
    for (int idx = tid; idx < MT*HPAD; idx += NTHREADS) sh[idx] = 0.f;

    // --- biases ---
    float b_r[2], b_z[2], b_in[2], b_hn[2];
    #pragma unroll
    for (int jj = 0; jj < 2; jj++) {
        int jg = jg0 + jj;
        b_r[jj]  = b_ih[jg]        + b_hh[jg];
        b_z[jj]  = b_ih[HID+jg]    + b_hh[HID+jg];
        b_in[jj] = b_ih[2*HID+jg];
        b_hn[jj] = b_hh[2*HID+jg];
    }

    // --- x(t=0) into buffer 0 ---
    {
        int r = tid >> 2, c = (tid & 3) << 4;
        const float4* src = (const float4*)(x_seq + ((size_t)(grp*MT + r))*TSTEPS*STATE_DIM + c);
        float4 a0 = src[0], a1 = src[1], a2 = src[2], a3 = src[3];
        float4* d = (float4*)(sx + r*XPAD + c);
        d[0]=a0; d[1]=a1; d[2]=a2; d[3]=a3;
    }

    // --- DSMEM broadcast destinations ---
    uint32_t sh_addr = smem_u32(sh);
    uint32_t dstb[CLUSTER_C];
    #pragma unroll
    for (int r2 = 0; r2 < CLUSTER_C; r2++)
        asm("mapa.shared::cluster.u32 %0, %1, %2;" : "=r"(dstb[r2]) : "r"(sh_addr), "r"(r2));

    const ulonglong2* sh4  = (const ulonglong2*)sh;   // row stride HPAD/4 = 65
    const ulonglong2* sWh4 = (const ulonglong2*)sWh;
    const ulonglong2* sWx4 = (const ulonglong2*)sWx;

    int whr[2], whz[2], whn[2], wxr[2], wxz[2], wxn[2];
    #pragma unroll
    for (int jj = 0; jj < 2; jj++) {
        int j = 2*tj + jj;
        whr[jj] = (0*HS + j)*(HPAD/4);
        whz[jj] = (1*HS + j)*(HPAD/4);
        whn[jj] = (2*HS + j)*(HPAD/4);
        wxr[jj] = (0*HS + j)*(XPAD/4);
        wxz[jj] = (1*HS + j)*(XPAD/4);
        wxn[jj] = (2*HS + j)*(XPAD/4);
    }

    float hnew[4][2];

    cluster_sync_();   // smem init done everywhere (h starts at 0)

    for (int t = 0; t < TSTEPS; t++) {
        const int p = t & 1;

        ull ar[4][2], az[4][2], an[4][2], anh[4][2];
        #pragma unroll
        for (int i = 0; i < 4; i++)
            #pragma unroll
            for (int jj = 0; jj < 2; jj++) { ar[i][jj]=0; az[i][jj]=0; an[i][jj]=0; anh[i][jj]=0; }

        // ---- A) x-part GEMM: K=64, LDS.128, independent of h(t) broadcast ----
        const ulonglong2* sxp = (const ulonglong2*)(sx + p*(MT*XPAD));
        #pragma unroll 2
        for (int k4 = 0; k4 < STATE_DIM/4; k4++) {
            ulonglong2 xv[4];
            #pragma unroll
            for (int i = 0; i < 4; i++) xv[i] = sxp[(tm + 16*i)*(XPAD/4) + k4];
            #pragma unroll
            for (int jj = 0; jj < 2; jj++) {
                ulonglong2 wr = sWx4[wxr[jj] + k4];
                ulonglong2 wz = sWx4[wxz[jj] + k4];
                ulonglong2 wn = sWx4[wxn[jj] + k4];
                #pragma unroll
                for (int i = 0; i < 4; i++) {
                    fma2(ar[i][jj], xv[i].x, wr.x); fma2(ar[i][jj], xv[i].y, wr.y);
                    fma2(az[i][jj], xv[i].x, wz.x); fma2(az[i][jj], xv[i].y, wz.y);
                    fma2(an[i][jj], xv[i].x, wn.x); fma2(an[i][jj], xv[i].y, wn.y);
                }
            }
        }

        // ---- B) prefetch x(t+1) into registers ----
        float4 a0, a1, a2, a3;
        const bool pf = (t+1 < TSTEPS);
        if (pf) {
            int r = tid >> 2, c = (tid & 3) << 4;
            const float4* src = (const float4*)(x_seq +
                (((size_t)(grp*MT + r))*TSTEPS + (t+1))*STATE_DIM + c);
            a0 = src[0]; a1 = src[1]; a2 = src[2]; a3 = src[3];
        }

        // ---- C) sync A: h(t) broadcast (from previous iteration) visible ----
        cluster_sync_();

        // ---- D) h-part GEMM: K=256, LDS.128 ----
        #pragma unroll 2
        for (int k4 = 0; k4 < HID/4; k4++) {
            ulonglong2 hv[4];
            #pragma unroll
            for (int i = 0; i < 4; i++) hv[i] = sh4[(tm + 16*i)*(HPAD/4) + k4];
            #pragma unroll
            for (int jj = 0; jj < 2; jj++) {
                ulonglong2 wr = sWh4[whr[jj] + k4];
                ulonglong2 wz = sWh4[whz[jj] + k4];
                ulonglong2 wn = sWh4[whn[jj] + k4];
                #pragma unroll
                for (int i = 0; i < 4; i++) {
                    fma2(ar[i][jj],  hv[i].x, wr.x); fma2(ar[i][jj],  hv[i].y, wr.y);
                    fma2(az[i][jj],  hv[i].x, wz.x); fma2(az[i][jj],  hv[i].y, wz.y);
                    fma2(anh[i][jj], hv[i].x, wn.x); fma2(anh[i][jj], hv[i].y, wn.y);
                }
            }
        }

        // ---- E) gates + state update ----
        #pragma unroll
        for (int i = 0; i < 4; i++)
            #pragma unroll
            for (int jj = 0; jj < 2; jj++) {
                float r = sigf(red2(ar[i][jj]) + b_r[jj]);
                float z = sigf(red2(az[i][jj]) + b_z[jj]);
                float n = tanhf_fast(red2(an[i][jj]) + b_in[jj]
                                     + r*(red2(anh[i][jj]) + b_hn[jj]));
                float hold = sh[(tm + 16*i)*HPAD + jg0 + jj];
                hnew[i][jj] = (1.f - z)*n + z*hold;
            }

        // ---- F) stage prefetched x(t+1) into the other buffer ----
        if (pf) {
            int r = tid >> 2, c = (tid & 3) << 4;
            float4* d = (float4*)(sx + (p^1)*(MT*XPAD) + r*XPAD + c);
            d[0]=a0; d[1]=a1; d[2]=a2; d[3]=a3;
        }

        // ---- G) sync B: all cluster CTAs done reading sh / sx ----
        cluster_sync_();

        // ---- H) broadcast h(t+1) slice to all 8 CTAs (drain overlaps next x-GEMM) ----
        #pragma unroll
        for (int i = 0; i < 4; i++) {
            ull v = pack2(hnew[i][0], hnew[i][1]);
            uint32_t off = ((uint32_t)(tm + 16*i)*HPAD + (uint32_t)jg0) * 4u;
            #pragma unroll
            for (int r2 = 0; r2 < CLUSTER_C; r2++)
                asm volatile("st.shared::cluster.u64 [%0], %1;"
                             :: "r"(dstb[r2] + off), "l"(v) : "memory");
        }
    }

    cluster_sync_();   // drain in-flight peer DSMEM stores before exit

    #pragma unroll
    for (int i = 0; i < 4; i++)
        #pragma unroll
        for (int jj = 0; jj < 2; jj++)
            g_hT[(size_t)(grp*MT + tm + 16*i)*HID + jg0 + jj] = hnew[i][jj];
}

// ---------------- heads ----------------
// 64 blocks x 16 batch rows: w_base re-read amortized 16x, float4 loads.
#define HROWS 16
__global__ void __launch_bounds__(256)
heads_kernel(const float* __restrict__ w_base, const float* __restrict__ b_base,
             const float* __restrict__ w_dir,  const float* __restrict__ b_dir,
             const float* __restrict__ w_mag,  const float* __restrict__ b_mag,
             float* __restrict__ out)
{
    __shared__ float shh[HROWS][HID];
    __shared__ float act[HROWS][AH];
    const int tid = threadIdx.x;
    const int blk = blockIdx.x;

    // load 16 h rows, coalesced
    {
        const float4* src = (const float4*)(g_hT + (size_t)blk*HROWS*HID);
        float4* dst = (float4*)&shh[0][0];
        #pragma unroll
        for (int i = 0; i < HROWS*HID/4/256; i++)
            dst[tid + 256*i] = src[tid + 256*i];
    }
    __syncthreads();

    // base layer: thread = unit u, computes all 16 rows
    {
        const int u = tid;
        float acc[HROWS];
        float bb = b_base[u];
        #pragma unroll
        for (int r = 0; r < HROWS; r++) acc[r] = bb;
        const float4* w4 = (const float4*)(w_base + (size_t)u*HID);
        #pragma unroll 4
        for (int k4 = 0; k4 < HID/4; k4++) {
            float4 w = w4[k4];
            #pragma unroll
            for (int r = 0; r < HROWS; r++) {
                const float4 h = *(const float4*)&shh[r][k4*4];
                acc[r] = fmaf(h.x, w.x, acc[r]);
                acc[r] = fmaf(h.y, w.y, acc[r]);
                acc[r] = fmaf(h.z, w.z, acc[r]);
                acc[r] = fmaf(h.w, w.w, acc[r]);
            }
        }
        #pragma unroll
        for (int r = 0; r < HROWS; r++) act[r][u] = fmaxf(acc[r], 0.f);
    }
    __syncthreads();

    // heads: 128 threads, (row, dim) pairs
    if (tid < HROWS*ADIM) {
        const int r = tid >> 3, d = tid & 7;
        float sd = b_dir[d], sm = b_mag[d];
        const float* wd = w_dir + (size_t)d*AH;
        const float* wm = w_mag + (size_t)d*AH;
        #pragma unroll 8
        for (int k = 0; k < AH; k++) {
            float a = act[r][k];
            sd = fmaf(a, wd[k], sd);
            sm = fmaf(a, wm[k], sm);
        }
        out[(blk*HROWS + r)*ADIM + d] = tanhf_fast(sd) * sigf(sm);
    }
}

// ---------------- launch ----------------
extern "C" void kernel_launch(void* const* d_in, const int* in_sizes, int n_in,
                              void* d_out, int out_size)
{
    (void)in_sizes; (void)n_in; (void)out_size;
    const float* x_seq  = (const float*)d_in[0];
    const float* w_ih   = (const float*)d_in[1];
    const float* w_hh   = (const float*)d_in[2];
    const float* b_ih   = (const float*)d_in[3];
    const float* b_hh   = (const float*)d_in[4];
    const float* w_base = (const float*)d_in[5];
    const float* b_base = (const float*)d_in[6];
    const float* w_dir  = (const float*)d_in[7];
    const float* b_dir  = (const float*)d_in[8];
    const float* w_mag  = (const float*)d_in[9];
    const float* b_mag  = (const float*)d_in[10];
    float* out = (float*)d_out;

    cudaFuncSetAttribute(gru_kernel, cudaFuncAttributeMaxDynamicSharedMemorySize, SMEM_BYTES);
    gru_kernel<<<GRID_SZ, NTHREADS, SMEM_BYTES>>>(x_seq, w_ih, w_hh, b_ih, b_hh);
    heads_kernel<<<BATCH/HROWS, 256>>>(w_base, b_base, w_dir, b_dir, w_mag, b_mag, out);
}